// round 8
// baseline (speedup 1.0000x reference)
#include <cuda_runtime.h>
#include <math.h>
#include <stdint.h>

// ---------------- problem constants ----------------
#define NMAX 40000
#define EMAX 640000
#define D    128
#define H    8
#define DK   16
#define T    3
#define R    4
#define NPT  8                       // nodes per tile in GEMM-ish kernels
#define MAXTILES (NMAX / NPT + T)    // 5003
#define NB   32                      // nodes per block in relation transform

// ---------------- device scratch (static: no allocation allowed) ----------------
__device__ float    g_k   [(size_t)NMAX * D];
__device__ float    g_q   [(size_t)NMAX * D];
__device__ float    g_v   [(size_t)NMAX * D];
__device__ float    g_s2u [(size_t)NMAX * D];
__device__ float    g_kr  [(size_t)NMAX * R * D];   // [n][r][h][f]
__device__ float    g_vr  [(size_t)NMAX * R * D];
__device__ float    g_raw [(size_t)EMAX * H];
__device__ float    g_ex  [(size_t)EMAX * H];
__device__ float    g_den [(size_t)NMAX * H];
__device__ unsigned g_max [(size_t)NMAX * H];
__device__ int      g_win [NMAX];
__device__ float    g_aggr[(size_t)NMAX * D];
__device__ float    g_Wf  [D * D];
__device__ float    g_bf  [D];
__device__ int      g_cnt [T];
__device__ int      g_pos [T];
__device__ int      g_order[NMAX];
__device__ int      g_tileStart[MAXTILES];
__device__ int      g_tileMeta [MAXTILES];  // cnt | (type<<8)
__device__ int      g_ntiles;

// ---------------- helpers ----------------
__device__ __forceinline__ unsigned fkey(float f) {
    int i = __float_as_int(f);
    return (i >= 0) ? ((unsigned)i | 0x80000000u) : ~((unsigned)i);
}
__device__ __forceinline__ float funkey(unsigned u) {
    int i = (u & 0x80000000u) ? (int)(u & 0x7fffffffu) : (int)(~u);
    return __int_as_float(i);
}
__device__ __forceinline__ void redv4(float* p, float a, float b, float c, float d) {
    // vector reduction to global (sm_90+): 1 instruction instead of 4 atomics
    asm volatile("red.global.add.v4.f32 [%0], {%1,%2,%3,%4};"
                 :: "l"(p), "f"(a), "f"(b), "f"(c), "f"(d) : "memory");
}

// ---------------- kernels ----------------

// Zero / init all per-launch scratch (graph replays must be deterministic)
__global__ void k_init(int N) {
    int i = blockIdx.x * blockDim.x + threadIdx.x;
    if (i < N * D)  g_aggr[i] = 0.f;
    if (i < N * H) { g_den[i] = 0.f; g_max[i] = 0u; }
    if (i < N)      g_win[i] = -1;
    if (i < T)     { g_cnt[i] = 0; g_pos[i] = 0; }
}

// Fuse Wf = Vw[1] @ S2U ; bf = Vb[1] @ S2U
__global__ void k_fuse(const float* __restrict__ Vw, const float* __restrict__ Vb,
                       const float* __restrict__ S2U) {
    int d = blockIdx.x;
    int o = threadIdx.x;
    if (d < D) {
        const float* w = Vw + D * D + d * D;   // Vw[1][d][:]
        float acc = 0.f;
        for (int m = 0; m < D; m++) acc += w[m] * S2U[m * D + o];
        g_Wf[d * D + o] = acc;
    } else {
        const float* b = Vb + D;               // Vb[1][:]
        float acc = 0.f;
        for (int m = 0; m < D; m++) acc += b[m] * S2U[m * D + o];
        g_bf[o] = acc;
    }
}

__global__ void k_count(const int* __restrict__ ntype, int N) {
    int i = blockIdx.x * blockDim.x + threadIdx.x;
    if (i < N) atomicAdd(&g_cnt[ntype[i]], 1);
}

// single block: bucket offsets + tile map
__global__ void k_scan(int N) {
    __shared__ int off[T + 1], toff[T + 1];
    if (threadIdx.x == 0) {
        off[0] = 0;
        for (int t = 0; t < T; t++) off[t + 1] = off[t] + g_cnt[t];
        toff[0] = 0;
        for (int t = 0; t < T; t++) toff[t + 1] = toff[t] + (g_cnt[t] + NPT - 1) / NPT;
        g_ntiles = toff[T];
        for (int t = 0; t < T; t++) g_pos[t] = off[t];
    }
    __syncthreads();
    int nt = toff[T];
    for (int i = threadIdx.x; i < nt; i += blockDim.x) {
        int t = 0;
        while (t < T - 1 && i >= toff[t + 1]) t++;
        int local = i - toff[t];
        int start = off[t] + local * NPT;
        int cnt   = min(NPT, off[t] + g_cnt[t] - start);
        g_tileStart[i] = start;
        g_tileMeta[i]  = cnt | (t << 8);
    }
}

__global__ void k_fill(const int* __restrict__ ntype, int N) {
    int i = blockIdx.x * blockDim.x + threadIdx.x;
    if (i < N) {
        int t = ntype[i];
        int p = atomicAdd(&g_pos[t], 1);
        g_order[p] = i;
    }
}

// Type-bucketed projections: k, q, v (own type), s2u (fused weight), 8 nodes/block
__global__ void __launch_bounds__(D) k_proj(
    const float* __restrict__ x,
    const float* __restrict__ Kw, const float* __restrict__ Kb,
    const float* __restrict__ Qw, const float* __restrict__ Qb,
    const float* __restrict__ Vw, const float* __restrict__ Vb) {
    int tile = blockIdx.x;
    if (tile >= g_ntiles) return;
    int start = g_tileStart[tile];
    int meta  = g_tileMeta[tile];
    int cnt   = meta & 0xff;
    int t     = meta >> 8;

    __shared__ float xs[NPT][D];
    int o = threadIdx.x;
    #pragma unroll
    for (int i = 0; i < NPT; i++) {
        int n = g_order[start + min(i, cnt - 1)];
        xs[i][o] = x[(size_t)n * D + o];
    }
    __syncthreads();

    const float* kw = Kw + t * D * D;
    const float* qw = Qw + t * D * D;
    const float* vw = Vw + t * D * D;

    float aK[NPT], aQ[NPT], aV[NPT], aS[NPT];
    float bKv = Kb[t * D + o], bQv = Qb[t * D + o], bVv = Vb[t * D + o], bSv = g_bf[o];
    #pragma unroll
    for (int i = 0; i < NPT; i++) { aK[i] = bKv; aQ[i] = bQv; aV[i] = bVv; aS[i] = bSv; }

    for (int d = 0; d < D; d++) {
        float wk = kw[d * D + o];
        float wq = qw[d * D + o];
        float wv = vw[d * D + o];
        float ws = g_Wf[d * D + o];
        #pragma unroll
        for (int i = 0; i < NPT; i++) {
            float xv = xs[i][d];
            aK[i] += xv * wk; aQ[i] += xv * wq;
            aV[i] += xv * wv; aS[i] += xv * ws;
        }
    }
    for (int i = 0; i < cnt; i++) {
        int n = g_order[start + i];
        g_k  [(size_t)n * D + o] = aK[i];
        g_q  [(size_t)n * D + o] = aQ[i];
        g_v  [(size_t)n * D + o] = aV[i];
        g_s2u[(size_t)n * D + o] = aS[i];
    }
}

// Per-node, per-relation head transform: dst[n][r][h][f] = sum_d src[n][h][d] * W[r][h][d][f]
// which==0: g_k -> g_kr (relation_att); which==1: g_v -> g_vr (relation_msg)
__global__ void __launch_bounds__(D) k_rel(const float* __restrict__ W, int which, int N) {
    __shared__ float sw[R * H * DK * 17];   // padded stride-17 to kill bank conflicts
    __shared__ float xr[D];
    int tid = threadIdx.x;
    for (int idx = tid; idx < R * H * DK * DK; idx += D) {
        int f = idx & 15, d = (idx >> 4) & 15, hh = (idx >> 8) & 7, r = idx >> 11;
        sw[((r * H + hh) * DK + d) * 17 + f] = W[idx];
    }
    __syncthreads();

    const float* src = which ? g_v : g_k;
    float*       dst = which ? g_vr : g_kr;
    int h = tid >> 4, f = tid & 15;
    int n0 = blockIdx.x * NB;

    for (int i = 0; i < NB; i++) {
        int n = n0 + i;
        if (n >= N) break;
        __syncthreads();
        xr[tid] = src[(size_t)n * D + tid];
        __syncthreads();
        #pragma unroll
        for (int r = 0; r < R; r++) {
            float acc = 0.f;
            #pragma unroll
            for (int d = 0; d < DK; d++)
                acc += xr[h * DK + d] * sw[((r * H + h) * DK + d) * 17 + f];
            dst[((size_t)n * R + r) * D + h * DK + f] = acc;
        }
    }
}

// Edge pass 1: att_raw + segment max + speaker winner
__global__ void k_att(const int* __restrict__ eidx, const int* __restrict__ etype,
                      const int* __restrict__ ntype, const float* __restrict__ pri, int E_) {
    int e = blockIdx.x * 256 + threadIdx.x;
    if (e >= E_) return;
    int src = eidx[e], tgt = eidx[E_ + e], r = etype[e];
    int st = ntype[src], tt = ntype[tgt];
    const float4* q4 = (const float4*)(g_q + (size_t)tgt * D);
    const float4* k4 = (const float4*)(g_kr + ((size_t)src * R + r) * D);
    const float*  pr = pri + (((size_t)tt * R + r) * T + st) * H;
    #pragma unroll
    for (int h = 0; h < H; h++) {
        float dot = 0.f;
        #pragma unroll
        for (int j = 0; j < 4; j++) {
            float4 a = q4[h * 4 + j], b = k4[h * 4 + j];
            dot += a.x * b.x + a.y * b.y + a.z * b.z + a.w * b.w;
        }
        float raw = dot * pr[h] * 0.25f;   // 1/sqrt(DK)
        g_raw[(size_t)e * H + h] = raw;
        atomicMax(&g_max[(size_t)tgt * H + h], fkey(raw));
    }
    if (r == 0) atomicMax(&g_win[src], e);   // last-write-wins emulation
}

// Edge pass 2: exp(raw - max) and segment sum
__global__ void k_exp(const int* __restrict__ eidx, int E_) {
    int e = blockIdx.x * 256 + threadIdx.x;
    if (e >= E_) return;
    int tgt = eidx[E_ + e];
    #pragma unroll
    for (int h = 0; h < H; h++) {
        float m  = funkey(g_max[(size_t)tgt * H + h]);
        float ex = expf(g_raw[(size_t)e * H + h] - m);
        g_ex[(size_t)e * H + h] = ex;
        atomicAdd(&g_den[(size_t)tgt * H + h], ex);
    }
}

// Edge pass 3: normalize, scatter messages, and add speaker info (winning edge only)
__global__ void k_aggr(const int* __restrict__ eidx, const int* __restrict__ etype, int E_) {
    int e = blockIdx.x * 256 + threadIdx.x;
    if (e >= E_) return;
    int src = eidx[e], tgt = eidx[E_ + e], r = etype[e];
    float att[H];
    #pragma unroll
    for (int h = 0; h < H; h++)
        att[h] = g_ex[(size_t)e * H + h] / (g_den[(size_t)tgt * H + h] + 1e-16f);

    const float4* v4 = (const float4*)(g_vr + ((size_t)src * R + r) * D);
    float* ag = g_aggr + (size_t)tgt * D;
    #pragma unroll
    for (int h = 0; h < H; h++) {
        float a = att[h];
        #pragma unroll
        for (int j = 0; j < 4; j++) {
            float4 v = v4[h * 4 + j];
            redv4(ag + h * DK + j * 4, v.x * a, v.y * a, v.z * a, v.w * a);
        }
    }
    if (r == 0 && g_win[src] == e) {
        const float4* s = (const float4*)(g_s2u + (size_t)tgt * D);
        float* as_ = g_aggr + (size_t)src * D;
        #pragma unroll 8
        for (int c = 0; c < 32; c++) {
            float4 v = s[c];
            redv4(as_ + c * 4, v.x, v.y, v.z, v.w);
        }
    }
}

// Final: gelu(aggr) @ Aw[type] + Ab[type], skip-blend, type-bucketed
__global__ void __launch_bounds__(D) k_out(
    const float* __restrict__ x, const float* __restrict__ Aw,
    const float* __restrict__ Ab, const float* __restrict__ skip,
    float* __restrict__ out) {
    int tile = blockIdx.x;
    if (tile >= g_ntiles) return;
    int start = g_tileStart[tile];
    int meta  = g_tileMeta[tile];
    int cnt   = meta & 0xff;
    int t     = meta >> 8;

    __shared__ float gs[NPT][D];
    int o = threadIdx.x;
    #pragma unroll
    for (int i = 0; i < NPT; i++) {
        int n = g_order[start + min(i, cnt - 1)];
        float a = g_aggr[(size_t)n * D + o];
        gs[i][o] = 0.5f * a * (1.0f + erff(a * 0.70710678118654752f));  // exact gelu
    }
    __syncthreads();

    const float* aw = Aw + t * D * D;
    float acc[NPT];
    float b = Ab[t * D + o];
    #pragma unroll
    for (int i = 0; i < NPT; i++) acc[i] = b;
    for (int d = 0; d < D; d++) {
        float w = aw[d * D + o];
        #pragma unroll
        for (int i = 0; i < NPT; i++) acc[i] += gs[i][d] * w;
    }
    float alpha = 1.f / (1.f + expf(-skip[t]));
    for (int i = 0; i < cnt; i++) {
        int n = g_order[start + i];
        out[(size_t)n * D + o] = acc[i] * alpha + x[(size_t)n * D + o] * (1.f - alpha);
    }
}

// ---------------- launch ----------------
extern "C" void kernel_launch(void* const* d_in, const int* in_sizes, int n_in,
                              void* d_out, int out_size) {
    const float* node_inp  = (const float*)d_in[0];
    const int*   node_type = (const int*)  d_in[1];
    const int*   edge_index= (const int*)  d_in[2];
    const int*   edge_type = (const int*)  d_in[3];
    // d_in[4] node_position: unused by reference
    const float* Kw  = (const float*)d_in[5];
    const float* Kb  = (const float*)d_in[6];
    const float* Qw  = (const float*)d_in[7];
    const float* Qb  = (const float*)d_in[8];
    const float* Vw  = (const float*)d_in[9];
    const float* Vb  = (const float*)d_in[10];
    const float* Aw  = (const float*)d_in[11];
    const float* Ab  = (const float*)d_in[12];
    const float* pri = (const float*)d_in[13];
    const float* Ratt= (const float*)d_in[14];
    const float* Rmsg= (const float*)d_in[15];
    const float* S2U = (const float*)d_in[16];
    const float* skp = (const float*)d_in[17];

    int N  = in_sizes[0] / D;
    int E_ = in_sizes[3];

    k_init <<<(N * D + 255) / 256, 256>>>(N);
    k_fuse <<<D + 1, D>>>(Vw, Vb, S2U);
    k_count<<<(N + 255) / 256, 256>>>(node_type, N);
    k_scan <<<1, 256>>>(N);
    k_fill <<<(N + 255) / 256, 256>>>(node_type, N);
    k_proj <<<MAXTILES, D>>>(node_inp, Kw, Kb, Qw, Qb, Vw, Vb);
    k_rel  <<<(N + NB - 1) / NB, D>>>(Ratt, 0, N);
    k_rel  <<<(N + NB - 1) / NB, D>>>(Rmsg, 1, N);
    k_att  <<<(E_ + 255) / 256, 256>>>(edge_index, edge_type, node_type, pri, E_);
    k_exp  <<<(E_ + 255) / 256, 256>>>(edge_index, E_);
    k_aggr <<<(E_ + 255) / 256, 256>>>(edge_index, edge_type, E_);
    k_out  <<<MAXTILES, D>>>(node_inp, Aw, Ab, skp, (float*)d_out);
}

// round 9
// speedup vs baseline: 1.2707x; 1.2707x over previous
#include <cuda_runtime.h>
#include <math.h>
#include <stdint.h>

// ---------------- problem constants ----------------
#define NMAX 40000
#define EMAX 640000
#define D    128
#define H    8
#define DK   16
#define T    3
#define R    4
#define NPT  16                      // nodes per tile in GEMM-ish kernels
#define MAXTILES (NMAX / NPT + T)
#define NB   32                      // nodes per block in relation transform

// ---------------- device scratch (static: no allocation allowed) ----------------
__device__ float    g_k   [(size_t)NMAX * D];
__device__ float    g_q   [(size_t)NMAX * D];
__device__ float    g_v   [(size_t)NMAX * D];
__device__ float    g_s2u [(size_t)NMAX * D];
__device__ float    g_kr  [(size_t)NMAX * R * D];   // [n][r][h][f]
__device__ float    g_vr  [(size_t)NMAX * R * D];
__device__ float    g_aggr[(size_t)NMAX * D];
__device__ int      g_win [NMAX];
__device__ float    g_Wf  [D * D];
__device__ float    g_bf  [D];
__device__ int      g_cnt [T];
__device__ int      g_pos [T];
__device__ int      g_order[NMAX];
__device__ int      g_tileStart[MAXTILES];
__device__ int      g_tileMeta [MAXTILES];  // cnt | (type<<8)
__device__ int      g_ntiles;
// CSR by target
__device__ int      g_deg   [NMAX];
__device__ int      g_rowptr[NMAX + 1];
__device__ int      g_cursor[NMAX];
__device__ int      g_csr   [EMAX];   // packed: src(16) | r(2)<<16 | st(2)<<18

// ---------------- kernels ----------------

// Zero / init all per-launch scratch (graph replays must be deterministic)
__global__ void k_init(int N) {
    int i = blockIdx.x * blockDim.x + threadIdx.x;
    if (i < N) { g_deg[i] = 0; g_win[i] = -1; }
    if (i < T) { g_cnt[i] = 0; g_pos[i] = 0; }
}

// Fuse Wf = Vw[1] @ S2U ; bf = Vb[1] @ S2U
__global__ void k_fuse(const float* __restrict__ Vw, const float* __restrict__ Vb,
                       const float* __restrict__ S2U) {
    int d = blockIdx.x;
    int o = threadIdx.x;
    if (d < D) {
        const float* w = Vw + D * D + d * D;   // Vw[1][d][:]
        float acc = 0.f;
        for (int m = 0; m < D; m++) acc += w[m] * S2U[m * D + o];
        g_Wf[d * D + o] = acc;
    } else {
        const float* b = Vb + D;               // Vb[1][:]
        float acc = 0.f;
        for (int m = 0; m < D; m++) acc += b[m] * S2U[m * D + o];
        g_bf[o] = acc;
    }
}

__global__ void k_count(const int* __restrict__ ntype, int N) {
    int i = blockIdx.x * blockDim.x + threadIdx.x;
    if (i < N) atomicAdd(&g_cnt[ntype[i]], 1);
}

// Edge degree count + speaker winner (last-write-wins = max edge id)
__global__ void k_deg(const int* __restrict__ eidx, const int* __restrict__ etype, int E_) {
    int e = blockIdx.x * blockDim.x + threadIdx.x;
    if (e >= E_) return;
    atomicAdd(&g_deg[eidx[E_ + e]], 1);
    if (etype[e] == 0) atomicMax(&g_win[eidx[e]], e);
}

// single block: type-bucket offsets + tile map
__global__ void k_scan(int N) {
    __shared__ int off[T + 1], toff[T + 1];
    if (threadIdx.x == 0) {
        off[0] = 0;
        for (int t = 0; t < T; t++) off[t + 1] = off[t] + g_cnt[t];
        toff[0] = 0;
        for (int t = 0; t < T; t++) toff[t + 1] = toff[t] + (g_cnt[t] + NPT - 1) / NPT;
        g_ntiles = toff[T];
        for (int t = 0; t < T; t++) g_pos[t] = off[t];
    }
    __syncthreads();
    int nt = toff[T];
    for (int i = threadIdx.x; i < nt; i += blockDim.x) {
        int t = 0;
        while (t < T - 1 && i >= toff[t + 1]) t++;
        int local = i - toff[t];
        int start = off[t] + local * NPT;
        int cnt   = min(NPT, off[t] + g_cnt[t] - start);
        g_tileStart[i] = start;
        g_tileMeta[i]  = cnt | (t << 8);
    }
}

// single block: exclusive prefix-scan of degrees -> rowptr + fill cursor
__global__ void k_scanE(int N) {
    __shared__ int sh[1024];
    __shared__ int carry;
    int tid = threadIdx.x;
    if (tid == 0) { carry = 0; g_rowptr[0] = 0; }
    __syncthreads();
    for (int base = 0; base < N; base += 1024) {
        int v = (base + tid < N) ? g_deg[base + tid] : 0;
        sh[tid] = v;
        __syncthreads();
        for (int ofs = 1; ofs < 1024; ofs <<= 1) {
            int t = (tid >= ofs) ? sh[tid - ofs] : 0;
            __syncthreads();
            sh[tid] += t;
            __syncthreads();
        }
        if (base + tid < N) {
            int inc = carry + sh[tid];
            g_rowptr[base + tid + 1] = inc;
            g_cursor[base + tid]     = inc - v;
        }
        __syncthreads();
        if (tid == 0) carry += sh[1023];
        __syncthreads();
    }
}

__global__ void k_fill(const int* __restrict__ ntype, int N) {
    int i = blockIdx.x * blockDim.x + threadIdx.x;
    if (i < N) {
        int t = ntype[i];
        int p = atomicAdd(&g_pos[t], 1);
        g_order[p] = i;
    }
}

// CSR fill: pack src | relation | src-type
__global__ void k_efill(const int* __restrict__ eidx, const int* __restrict__ etype,
                        const int* __restrict__ ntype, int E_) {
    int e = blockIdx.x * blockDim.x + threadIdx.x;
    if (e >= E_) return;
    int src = eidx[e], tgt = eidx[E_ + e], r = etype[e];
    int st  = ntype[src];
    int pos = atomicAdd(&g_cursor[tgt], 1);
    g_csr[pos] = src | (r << 16) | (st << 18);
}

// Type-bucketed projections: k, q, v (own type), s2u (fused weight), NPT nodes/block
__global__ void __launch_bounds__(D) k_proj(
    const float* __restrict__ x,
    const float* __restrict__ Kw, const float* __restrict__ Kb,
    const float* __restrict__ Qw, const float* __restrict__ Qb,
    const float* __restrict__ Vw, const float* __restrict__ Vb) {
    int tile = blockIdx.x;
    if (tile >= g_ntiles) return;
    int start = g_tileStart[tile];
    int meta  = g_tileMeta[tile];
    int cnt   = meta & 0xff;
    int t     = meta >> 8;

    __shared__ float xs[NPT][D];
    int o = threadIdx.x;
    #pragma unroll
    for (int i = 0; i < NPT; i++) {
        int n = g_order[start + min(i, cnt - 1)];
        xs[i][o] = x[(size_t)n * D + o];
    }
    __syncthreads();

    const float* kw = Kw + t * D * D;
    const float* qw = Qw + t * D * D;
    const float* vw = Vw + t * D * D;

    float aK[NPT], aQ[NPT], aV[NPT], aS[NPT];
    float bKv = Kb[t * D + o], bQv = Qb[t * D + o], bVv = Vb[t * D + o], bSv = g_bf[o];
    #pragma unroll
    for (int i = 0; i < NPT; i++) { aK[i] = bKv; aQ[i] = bQv; aV[i] = bVv; aS[i] = bSv; }

    for (int d = 0; d < D; d++) {
        float wk = kw[d * D + o];
        float wq = qw[d * D + o];
        float wv = vw[d * D + o];
        float ws = g_Wf[d * D + o];
        #pragma unroll
        for (int i = 0; i < NPT; i++) {
            float xv = xs[i][d];
            aK[i] += xv * wk; aQ[i] += xv * wq;
            aV[i] += xv * wv; aS[i] += xv * ws;
        }
    }
    for (int i = 0; i < cnt; i++) {
        int n = g_order[start + i];
        g_k  [(size_t)n * D + o] = aK[i];
        g_q  [(size_t)n * D + o] = aQ[i];
        g_v  [(size_t)n * D + o] = aV[i];
        g_s2u[(size_t)n * D + o] = aS[i];
    }
}

// Per-node, per-relation head transform
__global__ void __launch_bounds__(D) k_rel(const float* __restrict__ W, int which, int N) {
    __shared__ float sw[R * H * DK * 17];
    __shared__ float xr[D];
    int tid = threadIdx.x;
    for (int idx = tid; idx < R * H * DK * DK; idx += D) {
        int f = idx & 15, d = (idx >> 4) & 15, hh = (idx >> 8) & 7, r = idx >> 11;
        sw[((r * H + hh) * DK + d) * 17 + f] = W[idx];
    }
    __syncthreads();

    const float* src = which ? g_v : g_k;
    float*       dst = which ? g_vr : g_kr;
    int h = tid >> 4, f = tid & 15;
    int n0 = blockIdx.x * NB;

    for (int i = 0; i < NB; i++) {
        int n = n0 + i;
        if (n >= N) break;
        __syncthreads();
        xr[tid] = src[(size_t)n * D + tid];
        __syncthreads();
        #pragma unroll
        for (int r = 0; r < R; r++) {
            float acc = 0.f;
            #pragma unroll
            for (int d = 0; d < DK; d++)
                acc += xr[h * DK + d] * sw[((r * H + h) * DK + d) * 17 + f];
            dst[((size_t)n * R + r) * D + h * DK + f] = acc;
        }
    }
}

// FUSED edge pass: warp per target node, online softmax, zero atomics.
// lane l -> head h=l>>2, dims [4l, 4l+3].
__global__ void __launch_bounds__(256) k_edge(const int* __restrict__ ntype,
                                              const float* __restrict__ pri, int N) {
    __shared__ float spri[T * R * T * H];  // 288 floats
    int tid = threadIdx.x;
    for (int i = tid; i < T * R * T * H; i += 256) spri[i] = pri[i];
    __syncthreads();

    int n = blockIdx.x * 8 + (tid >> 5);
    if (n >= N) return;
    int lane = tid & 31;
    int h = lane >> 2;
    int tt = ntype[n];

    float4 q4 = *(const float4*)(g_q + (size_t)n * D + lane * 4);
    int beg = g_rowptr[n], end = g_rowptr[n + 1];

    float m = -INFINITY, den = 0.f;
    float4 acc = make_float4(0.f, 0.f, 0.f, 0.f);

    for (int j = beg; j < end; j++) {
        int pk  = g_csr[j];
        int src = pk & 0xFFFF;
        int r   = (pk >> 16) & 3;
        int st  = (pk >> 18) & 3;
        size_t base = ((size_t)src * R + r) * D + lane * 4;
        float4 k4 = *(const float4*)(g_kr + base);
        float4 v4 = *(const float4*)(g_vr + base);
        float dot = q4.x * k4.x + q4.y * k4.y + q4.z * k4.z + q4.w * k4.w;
        dot += __shfl_xor_sync(0xffffffffu, dot, 1);
        dot += __shfl_xor_sync(0xffffffffu, dot, 2);   // all 4 lanes of head group have dot
        float raw = dot * spri[((tt * R + r) * T + st) * H + h] * 0.25f; // 1/sqrt(DK)

        float mn = fmaxf(m, raw);
        float s  = __expf(m - mn);       // first iter: exp(-inf)=0
        float p  = __expf(raw - mn);
        den   = den * s + p;
        acc.x = acc.x * s + p * v4.x;
        acc.y = acc.y * s + p * v4.y;
        acc.z = acc.z * s + p * v4.z;
        acc.w = acc.w * s + p * v4.w;
        m = mn;
    }
    float inv = 1.f / (den + 1e-16f);
    float4 outv = make_float4(acc.x * inv, acc.y * inv, acc.z * inv, acc.w * inv);
    *(float4*)(g_aggr + (size_t)n * D + lane * 4) = outv;
}

// Speaker info: warp per edge, only winning (etype==0, max edge id per src) edges
// RMW into g_aggr (unique src per winner -> race-free).
__global__ void __launch_bounds__(256) k_spk(const int* __restrict__ eidx,
                                             const int* __restrict__ etype, int E_) {
    int e = blockIdx.x * 8 + (threadIdx.x >> 5);
    if (e >= E_) return;
    if (etype[e] != 0) return;
    int src = eidx[e];
    if (g_win[src] != e) return;
    int tgt  = eidx[E_ + e];
    int lane = threadIdx.x & 31;
    float4 s = *(const float4*)(g_s2u + (size_t)tgt * D + lane * 4);
    float* a = g_aggr + (size_t)src * D + lane * 4;
    float4 c = *(float4*)a;
    c.x += s.x; c.y += s.y; c.z += s.z; c.w += s.w;
    *(float4*)a = c;
}

// Final: gelu(aggr) @ Aw[type] + Ab[type], skip-blend, type-bucketed
__global__ void __launch_bounds__(D) k_out(
    const float* __restrict__ x, const float* __restrict__ Aw,
    const float* __restrict__ Ab, const float* __restrict__ skip,
    float* __restrict__ out) {
    int tile = blockIdx.x;
    if (tile >= g_ntiles) return;
    int start = g_tileStart[tile];
    int meta  = g_tileMeta[tile];
    int cnt   = meta & 0xff;
    int t     = meta >> 8;

    __shared__ float gs[NPT][D];
    int o = threadIdx.x;
    #pragma unroll
    for (int i = 0; i < NPT; i++) {
        int n = g_order[start + min(i, cnt - 1)];
        float a = g_aggr[(size_t)n * D + o];
        gs[i][o] = 0.5f * a * (1.0f + erff(a * 0.70710678118654752f));  // exact gelu
    }
    __syncthreads();

    const float* aw = Aw + t * D * D;
    float acc[NPT];
    float b = Ab[t * D + o];
    #pragma unroll
    for (int i = 0; i < NPT; i++) acc[i] = b;
    for (int d = 0; d < D; d++) {
        float w = aw[d * D + o];
        #pragma unroll
        for (int i = 0; i < NPT; i++) acc[i] += gs[i][d] * w;
    }
    float alpha = 1.f / (1.f + expf(-skip[t]));
    for (int i = 0; i < cnt; i++) {
        int n = g_order[start + i];
        out[(size_t)n * D + o] = acc[i] * alpha + x[(size_t)n * D + o] * (1.f - alpha);
    }
}

// ---------------- launch ----------------
extern "C" void kernel_launch(void* const* d_in, const int* in_sizes, int n_in,
                              void* d_out, int out_size) {
    const float* node_inp  = (const float*)d_in[0];
    const int*   node_type = (const int*)  d_in[1];
    const int*   edge_index= (const int*)  d_in[2];
    const int*   edge_type = (const int*)  d_in[3];
    // d_in[4] node_position: unused by reference
    const float* Kw  = (const float*)d_in[5];
    const float* Kb  = (const float*)d_in[6];
    const float* Qw  = (const float*)d_in[7];
    const float* Qb  = (const float*)d_in[8];
    const float* Vw  = (const float*)d_in[9];
    const float* Vb  = (const float*)d_in[10];
    const float* Aw  = (const float*)d_in[11];
    const float* Ab  = (const float*)d_in[12];
    const float* pri = (const float*)d_in[13];
    const float* Ratt= (const float*)d_in[14];
    const float* Rmsg= (const float*)d_in[15];
    const float* S2U = (const float*)d_in[16];
    const float* skp = (const float*)d_in[17];

    int N  = in_sizes[0] / D;
    int E_ = in_sizes[3];

    k_init <<<(N + 255) / 256, 256>>>(N);
    k_fuse <<<D + 1, D>>>(Vw, Vb, S2U);
    k_count<<<(N + 255) / 256, 256>>>(node_type, N);
    k_deg  <<<(E_ + 255) / 256, 256>>>(edge_index, edge_type, E_);
    k_scan <<<1, 256>>>(N);
    k_scanE<<<1, 1024>>>(N);
    k_fill <<<(N + 255) / 256, 256>>>(node_type, N);
    k_efill<<<(E_ + 255) / 256, 256>>>(edge_index, edge_type, node_type, E_);
    k_proj <<<MAXTILES, D>>>(node_inp, Kw, Kb, Qw, Qb, Vw, Vb);
    k_rel  <<<(N + NB - 1) / NB, D>>>(Ratt, 0, N);
    k_rel  <<<(N + NB - 1) / NB, D>>>(Rmsg, 1, N);
    k_edge <<<(N + 7) / 8, 256>>>(node_type, pri, N);
    k_spk  <<<(E_ + 7) / 8, 256>>>(edge_index, edge_type, E_);
    k_out  <<<MAXTILES, D>>>(node_inp, Aw, Ab, skp, (float*)d_out);
}